// round 7
// baseline (speedup 1.0000x reference)
#include <cuda_runtime.h>

// RK4 over tiny MLP (3 -> 8 -> 1, ReLU), per-row, fp32.
// R6:
//  - Weights packed on-device into u64 lane-pairs, copied to __constant__
//    (graph-capturable: pack kernel -> cudaMemcpyToSymbolAsync D2D -> main).
//    Warp-uniform weights ride the const-cache/UR path instead of 41 GPRs,
//    breaking the occupancy-vs-residency tension of R1/R4/R5.
//  - fma.rn.f32x2 on bare u64 ("l" constraints, no mov glue).
//  - ReLU: unpack + 2x fmaxf (FMNMX, alu pipe) + pack; max.f32x2 doesn't
//    exist on sm_100 (R5 ptxas error).

typedef unsigned long long u64;

#define DT       0.25f
#define HALF_DT  0.125f
#define DT6      (0.25f / 6.0f)

__device__ __forceinline__ u64 pack2(float lo, float hi) {
    u64 r;
    asm("mov.b64 %0, {%1, %2};" : "=l"(r) : "f"(lo), "f"(hi));
    return r;
}
__device__ __forceinline__ void unpack2(u64 v, float& lo, float& hi) {
    asm("mov.b64 {%0, %1}, %2;" : "=f"(lo), "=f"(hi) : "l"(v));
}
__device__ __forceinline__ u64 ffma2(u64 a, u64 b, u64 c) {
    u64 d;
    asm("fma.rn.f32x2 %0, %1, %2, %3;" : "=l"(d) : "l"(a), "l"(b), "l"(c));
    return d;
}
// ReLU on a packed pair: unpack halves (identity movs if ptxas aligns the
// pair), scalar FMNMX per lane, repack.
__device__ __forceinline__ u64 relu2(u64 t) {
    float lo, hi;
    unpack2(t, lo, hi);
    lo = fmaxf(lo, 0.0f);
    hi = fmaxf(hi, 0.0f);
    return pack2(lo, hi);
}

// __constant__ packed weights: [0:4)=w0, [4:8)=w1, [8:12)=w2,
// [12:16)=b1, [16:20)=W2(v), [20]=(b2,0)
__constant__ u64 cW[21];
__device__ u64 g_packed[21];

__global__ void pack_weights_kernel(const float* __restrict__ W1,
                                    const float* __restrict__ b1,
                                    const float* __restrict__ W2,
                                    const float* __restrict__ b2)
{
    if (threadIdx.x == 0 && blockIdx.x == 0) {
#pragma unroll
        for (int k = 0; k < 4; k++) {
            int j0 = 2 * k, j1 = 2 * k + 1;
            g_packed[0  + k] = pack2(W1[3 * j0 + 0], W1[3 * j1 + 0]);  // y0 coef
            g_packed[4  + k] = pack2(W1[3 * j0 + 1], W1[3 * j1 + 1]);  // y1 coef
            g_packed[8  + k] = pack2(W1[3 * j0 + 2], W1[3 * j1 + 2]);  // y2 coef
            g_packed[12 + k] = pack2(b1[j0], b1[j1]);
            g_packed[16 + k] = pack2(W2[j0], W2[j1]);
        }
        g_packed[20] = pack2(b2[0], 0.0f);
    }
}

// One RK4 stage: k = b2 + sum_j v_j * relu(w0_j*y0s + c_j)
__device__ __forceinline__ float mlp_eval(const u64 (&C)[4], float y0s) {
    u64 ys  = pack2(y0s, y0s);
    u64 acc = cW[20];
#pragma unroll
    for (int k = 0; k < 4; k++) {
        u64 t = relu2(ffma2(cW[0 + k], ys, C[k]));
        acc = ffma2(cW[16 + k], t, acc);
    }
    float lo, hi;
    unpack2(acc, lo, hi);
    return lo + hi;
}

__device__ __forceinline__ float rk4_row(float y0, float y1, float y2) {
    // Per-row constants c_j = b1_j + w1_j*y1 + w2_j*y2 (amortized over 4 stages)
    u64 y1b = pack2(y1, y1);
    u64 y2b = pack2(y2, y2);
    u64 C[4];
#pragma unroll
    for (int k = 0; k < 4; k++)
        C[k] = ffma2(cW[8 + k], y2b, ffma2(cW[4 + k], y1b, cW[12 + k]));

    float k1 = mlp_eval(C, y0);
    float k2 = mlp_eval(C, fmaf(HALF_DT, k1, y0));
    float k3 = mlp_eval(C, fmaf(HALF_DT, k2, y0));
    float k4 = mlp_eval(C, fmaf(DT, k3, y0));

    float s = fmaf(2.0f, k2 + k3, k1 + k4);
    return fmaf(DT6, s, y0);
}

template <bool GUARDED>
__global__ void __launch_bounds__(256, 6)
node_rk4_kernel(const float* __restrict__ x,
                float* __restrict__ out,
                int ngroups)   // ngroups = rows/4
{
    const float4* x4   = reinterpret_cast<const float4*>(x);
    float4*       out4 = reinterpret_cast<float4*>(out);

    int g = blockIdx.x * blockDim.x + threadIdx.x;
    const int stride = gridDim.x * blockDim.x;

#pragma unroll
    for (int it = 0; it < 4; it++, g += stride) {
        if (!GUARDED || g < ngroups) {
            // 4 rows = 12 floats = 3 coalesced float4 loads
            float4 fa = __ldg(&x4[3 * g + 0]);
            float4 fb = __ldg(&x4[3 * g + 1]);
            float4 fc = __ldg(&x4[3 * g + 2]);

            float r0 = rk4_row(fa.x, fa.y, fa.z);
            float r1 = rk4_row(fa.w, fb.x, fb.y);
            float r2 = rk4_row(fb.z, fb.w, fc.x);
            float r3 = rk4_row(fc.y, fc.z, fc.w);

            out4[g] = make_float4(r0, r1, r2, r3);
        }
    }
}

extern "C" void kernel_launch(void* const* d_in, const int* in_sizes, int n_in,
                              void* d_out, int out_size)
{
    const float* x  = (const float*)d_in[0];
    const float* W1 = (const float*)d_in[1];
    const float* b1 = (const float*)d_in[2];
    const float* W2 = (const float*)d_in[3];
    const float* b2 = (const float*)d_in[4];
    float* out = (float*)d_out;

    // 1) Pack weights into lane-pair u64s (device side).
    pack_weights_kernel<<<1, 32>>>(W1, b1, W2, b2);

    // 2) Stage packed weights into __constant__ (D2D async copy; capturable).
    void* packed_addr = nullptr;
    cudaGetSymbolAddress(&packed_addr, g_packed);
    cudaMemcpyToSymbolAsync(cW, packed_addr, 21 * sizeof(u64), 0,
                            cudaMemcpyDeviceToDevice, 0);

    // 3) Main compute.
    int rows    = in_sizes[0] / 3;       // 8388608
    int ngroups = rows / 4;
    int block = 256;
    int total_threads = (ngroups + 3) / 4;   // 4 groups (16 rows) per thread
    int grid  = (total_threads + block - 1) / block;

    bool exact = (rows % 4 == 0) &&
                 (ngroups % 4 == 0) &&
                 ((long long)grid * block * 4 == (long long)ngroups);

    if (exact)
        node_rk4_kernel<false><<<grid, block>>>(x, out, ngroups);
    else
        node_rk4_kernel<true ><<<grid, block>>>(x, out, ngroups);
}

// round 8
// speedup vs baseline: 1.1034x; 1.1034x over previous
#include <cuda_runtime.h>

// RK4 over tiny MLP (3 -> 8 -> 1, ReLU), per-row, fp32.
// R7:
//  - SINGLE kernel (R6's pack-kernel + memcpyToSymbol graph nodes cost 5.8us
//    per replay; main kernel alone was 35.2us).
//  - Swap-broadcast stage chaining: horizontal sum via lane-swap + add.f32x2
//    keeps k broadcast in a pair; next stage input = one ffma2. No per-stage
//    unpack/scalar-add/repack.
//  - fma.rn.f32x2 / add.rn.f32x2 on bare u64 ("l" constraints).

typedef unsigned long long u64;

#define DT       0.25f
#define HALF_DT  0.125f
#define DT6      (0.25f / 6.0f)

__device__ __forceinline__ u64 pack2(float lo, float hi) {
    u64 r;
    asm("mov.b64 %0, {%1, %2};" : "=l"(r) : "f"(lo), "f"(hi));
    return r;
}
__device__ __forceinline__ void unpack2(u64 v, float& lo, float& hi) {
    asm("mov.b64 {%0, %1}, %2;" : "=f"(lo), "=f"(hi) : "l"(v));
}
__device__ __forceinline__ u64 ffma2(u64 a, u64 b, u64 c) {
    u64 d;
    asm("fma.rn.f32x2 %0, %1, %2, %3;" : "=l"(d) : "l"(a), "l"(b), "l"(c));
    return d;
}
__device__ __forceinline__ u64 add2(u64 a, u64 b) {
    u64 d;
    asm("add.rn.f32x2 %0, %1, %2;" : "=l"(d) : "l"(a), "l"(b));
    return d;
}
__device__ __forceinline__ u64 relu2(u64 t) {
    float lo, hi;
    unpack2(t, lo, hi);
    lo = fmaxf(lo, 0.0f);
    hi = fmaxf(hi, 0.0f);
    return pack2(lo, hi);
}
// (lo+hi, hi+lo): broadcast horizontal sum via lane swap + packed add.
__device__ __forceinline__ u64 bcast_sum(u64 acc) {
    float lo, hi;
    unpack2(acc, lo, hi);
    return add2(acc, pack2(hi, lo));
}
__device__ __forceinline__ float lo_of(u64 v) {
    float lo, hi;
    unpack2(v, lo, hi);
    return lo;
}

struct WeightsP {
    u64 w0[4];   // y0 coefficients, lanes = hidden units (2k, 2k+1)
    u64 w1[4];   // y1 coefficients
    u64 w2[4];   // y2 coefficients
    u64 bb[4];   // b1
    u64 v[4];    // W2
    u64 b2p;     // (b2, 0)
};

// MLP accumulator for one stage input (broadcast pair ys):
// acc = (b2,0) + sum_k v_k * relu(w0_k*ys + C_k)   [lanes = unit pairs]
__device__ __forceinline__ u64 mlp_acc(const WeightsP& W, const u64 (&C)[4], u64 ys) {
    u64 acc = W.b2p;
#pragma unroll
    for (int k = 0; k < 4; k++) {
        u64 t = relu2(ffma2(W.w0[k], ys, C[k]));
        acc = ffma2(W.v[k], t, acc);
    }
    return acc;
}

__device__ __forceinline__ float rk4_row(const WeightsP& W, float y0, float y1, float y2) {
    const u64 hdtp = pack2(HALF_DT, HALF_DT);
    const u64 dtp  = pack2(DT, DT);

    u64 y0p = pack2(y0, y0);
    u64 y1b = pack2(y1, y1);
    u64 y2b = pack2(y2, y2);

    // Per-row constants c_j = b1_j + w1_j*y1 + w2_j*y2 (amortized over 4 stages)
    u64 C[4];
#pragma unroll
    for (int k = 0; k < 4; k++)
        C[k] = ffma2(W.w2[k], y2b, ffma2(W.w1[k], y1b, W.bb[k]));

    // Stage 1..3: broadcast k, chain next input with one packed fma.
    u64 s1  = bcast_sum(mlp_acc(W, C, y0p));            // (k1,k1)
    u64 ys2 = ffma2(hdtp, s1, y0p);
    u64 s2  = bcast_sum(mlp_acc(W, C, ys2));            // (k2,k2)
    u64 ys3 = ffma2(hdtp, s2, y0p);
    u64 s3  = bcast_sum(mlp_acc(W, C, ys3));            // (k3,k3)
    u64 ys4 = ffma2(dtp, s3, y0p);
    u64 a4  = mlp_acc(W, C, ys4);                       // no broadcast needed

    float k1 = lo_of(s1);
    float k2 = lo_of(s2);
    float k3 = lo_of(s3);
    float l4, h4;
    unpack2(a4, l4, h4);
    float k4 = l4 + h4;

    float K = fmaf(2.0f, k2 + k3, k1 + k4);
    return fmaf(DT6, K, y0);
}

template <bool GUARDED>
__global__ void __launch_bounds__(256, 5)
node_rk4_kernel(const float* __restrict__ x,
                const float* __restrict__ W1,
                const float* __restrict__ b1,
                const float* __restrict__ W2,
                const float* __restrict__ b2,
                float* __restrict__ out,
                int ngroups)   // ngroups = rows/4
{
    // ---- Load + pack weights once per thread (lane-uniform -> L1 broadcast) ----
    const float4* W14 = reinterpret_cast<const float4*>(W1);
    float4 wA = __ldg(&W14[0]);
    float4 wB = __ldg(&W14[1]);
    float4 wC = __ldg(&W14[2]);
    float4 wD = __ldg(&W14[3]);
    float4 wE = __ldg(&W14[4]);
    float4 wF = __ldg(&W14[5]);
    const float4* b14 = reinterpret_cast<const float4*>(b1);
    float4 bA = __ldg(&b14[0]);
    float4 bB = __ldg(&b14[1]);
    const float4* W24 = reinterpret_cast<const float4*>(W2);
    float4 vA = __ldg(&W24[0]);
    float4 vB = __ldg(&W24[1]);

    WeightsP W;
    W.w0[0] = pack2(wA.x, wA.w);
    W.w0[1] = pack2(wB.z, wC.y);
    W.w0[2] = pack2(wD.x, wD.w);
    W.w0[3] = pack2(wE.z, wF.y);

    W.w1[0] = pack2(wA.y, wB.x);
    W.w1[1] = pack2(wB.w, wC.z);
    W.w1[2] = pack2(wD.y, wE.x);
    W.w1[3] = pack2(wE.w, wF.z);

    W.w2[0] = pack2(wA.z, wB.y);
    W.w2[1] = pack2(wC.x, wC.w);
    W.w2[2] = pack2(wD.z, wE.y);
    W.w2[3] = pack2(wF.x, wF.w);

    W.bb[0] = pack2(bA.x, bA.y);
    W.bb[1] = pack2(bA.z, bA.w);
    W.bb[2] = pack2(bB.x, bB.y);
    W.bb[3] = pack2(bB.z, bB.w);

    W.v[0] = pack2(vA.x, vA.y);
    W.v[1] = pack2(vA.z, vA.w);
    W.v[2] = pack2(vB.x, vB.y);
    W.v[3] = pack2(vB.z, vB.w);

    W.b2p = pack2(__ldg(b2), 0.0f);

    const float4* x4   = reinterpret_cast<const float4*>(x);
    float4*       out4 = reinterpret_cast<float4*>(out);

    int g = blockIdx.x * blockDim.x + threadIdx.x;
    const int stride = gridDim.x * blockDim.x;

#pragma unroll
    for (int it = 0; it < 4; it++, g += stride) {
        if (!GUARDED || g < ngroups) {
            // 4 rows = 12 floats = 3 coalesced float4 loads
            float4 fa = __ldg(&x4[3 * g + 0]);
            float4 fb = __ldg(&x4[3 * g + 1]);
            float4 fc = __ldg(&x4[3 * g + 2]);

            float r0 = rk4_row(W, fa.x, fa.y, fa.z);
            float r1 = rk4_row(W, fa.w, fb.x, fb.y);
            float r2 = rk4_row(W, fb.z, fb.w, fc.x);
            float r3 = rk4_row(W, fc.y, fc.z, fc.w);

            out4[g] = make_float4(r0, r1, r2, r3);
        }
    }
}

extern "C" void kernel_launch(void* const* d_in, const int* in_sizes, int n_in,
                              void* d_out, int out_size)
{
    const float* x  = (const float*)d_in[0];
    const float* W1 = (const float*)d_in[1];
    const float* b1 = (const float*)d_in[2];
    const float* W2 = (const float*)d_in[3];
    const float* b2 = (const float*)d_in[4];
    float* out = (float*)d_out;

    int rows    = in_sizes[0] / 3;       // 8388608
    int ngroups = rows / 4;
    int block = 256;
    int total_threads = (ngroups + 3) / 4;   // 4 groups (16 rows) per thread
    int grid  = (total_threads + block - 1) / block;

    bool exact = (rows % 4 == 0) &&
                 (ngroups % 4 == 0) &&
                 ((long long)grid * block * 4 == (long long)ngroups);

    if (exact)
        node_rk4_kernel<false><<<grid, block>>>(x, W1, b1, W2, b2, out, ngroups);
    else
        node_rk4_kernel<true ><<<grid, block>>>(x, W1, b1, W2, b2, out, ngroups);
}